// round 11
// baseline (speedup 1.0000x reference)
#include <cuda_runtime.h>

#define BATCH   64
#define NPTS    4096
#define CHUNKS  4
#define NFRAMES 100
#define FSPLIT  4
#define FPER    (NFRAMES / FSPLIT)   // 25 frames per CTA
#define TPB     128
#define KPT     8   // NPTS / (CHUNKS*TPB)
#define GRID    (BATCH * CHUNKS * FSPLIT)

__device__ double g_sum;
__device__ double g_msum;
__device__ unsigned int g_count;

__device__ __forceinline__ float sqrt_approx(float x) {
    float r;
    asm("sqrt.approx.f32 %0, %1;" : "=f"(r) : "f"(x));
    return r;
}
// min(sqrt(s),10) == sqrt(min(|s|,100)); |s| handles tiny negative s from
// cancellation (|err| ~1e-5) — folds to a single FMNMX with abs modifier.
__device__ __forceinline__ float clamp_s(float s) {
    return fminf(fabsf(s), 100.f);
}

__global__ void __launch_bounds__(TPB) fape_kernel(
    const float* __restrict__ pred, const float* __restrict__ tru,
    const float* __restrict__ mask, float* __restrict__ out)
{
    // Frame constants for this CTA's 25-frame slice:
    //   sf[f] = (-2*e_fx, -2*e_fy, -2*e_fz, ||e_f||^2 + eps)
    __shared__ float4 sf[FPER];
    __shared__ float wsum[TPB / 32], wm[TPB / 32];

    const int b     = blockIdx.x >> 4;
    const int chunk = (blockIdx.x >> 2) & 3;
    const int fh    = blockIdx.x & 3;
    const int tid   = threadIdx.x;

    const float* pb = pred + (size_t)b * NPTS * 3;
    const float* tb = tru  + (size_t)b * NPTS * 3;
    const float* mb = mask + (size_t)b * NPTS;

    if (tid < FPER) {
        int f = fh * FPER + tid;
        float ex = pb[3 * f + 0] - tb[3 * f + 0];
        float ey = pb[3 * f + 1] - tb[3 * f + 1];
        float ez = pb[3 * f + 2] - tb[3 * f + 2];
        float nf = fmaf(ex, ex, fmaf(ey, ey, ez * ez)) + 1e-8f;
        sf[tid] = make_float4(-2.f * ex, -2.f * ey, -2.f * ez, nf);
    }
    __syncthreads();

    // Eight k-points per thread (independent chains -> ILP for ptxas)
    const int kbase = chunk * (TPB * KPT) + tid;
    float ex[KPT], ey[KPT], ez[KPT], nn[KPT], acc[KPT];
#pragma unroll
    for (int j = 0; j < KPT; ++j) {
        int k = kbase + j * TPB;
        ex[j] = pb[3 * k + 0] - tb[3 * k + 0];
        ey[j] = pb[3 * k + 1] - tb[3 * k + 1];
        ez[j] = pb[3 * k + 2] - tb[3 * k + 2];
        nn[j] = fmaf(ex[j], ex[j], fmaf(ey[j], ey[j], ez[j] * ez[j]));
        acc[j] = 0.f;
    }

#pragma unroll 5
    for (int f = 0; f < FPER; ++f) {
        float4 F = sf[f];
#pragma unroll
        for (int j = 0; j < KPT; ++j) {
            // s = n_k + (n_f + eps) + e_k . (-2 e_f)
            float s = fmaf(ex[j], F.x, fmaf(ey[j], F.y, fmaf(ez[j], F.z, nn[j] + F.w)));
            acc[j] += sqrt_approx(clamp_s(s));
        }
    }

    float tsum = 0.f, msum = 0.f;
#pragma unroll
    for (int j = 0; j < KPT; ++j) {
        float m = mb[kbase + j * TPB];
        tsum = fmaf(m, acc[j], tsum);
        msum += m;
    }
    // mask sum counted once (frame-split duplicates k-coverage): only fh==0 counts
    if (fh != 0) msum = 0.f;

    // warp reduce
#pragma unroll
    for (int off = 16; off; off >>= 1) {
        tsum += __shfl_down_sync(0xffffffffu, tsum, off);
        msum += __shfl_down_sync(0xffffffffu, msum, off);
    }
    int wid = tid >> 5, lane = tid & 31;
    if (lane == 0) { wsum[wid] = tsum; wm[wid] = msum; }
    __syncthreads();

    if (wid == 0 && lane == 0) {
        float ts = 0.f, ms = 0.f;
#pragma unroll
        for (int w = 0; w < TPB / 32; ++w) { ts += wsum[w]; ms += wm[w]; }
        atomicAdd(&g_sum, (double)ts);
        atomicAdd(&g_msum, (double)ms);
        __threadfence();
        unsigned int done = atomicAdd(&g_count, 1u);
        if (done == GRID - 1) {
            // last CTA: finalize and reset scratch for next graph replay
            double s = atomicAdd(&g_sum, 0.0);
            double m = atomicAdd(&g_msum, 0.0);
            out[0] = (float)((s / 10.0) / (m + 1e-8));
            g_sum = 0.0;
            g_msum = 0.0;
            g_count = 0u;
        }
    }
}

extern "C" void kernel_launch(void* const* d_in, const int* in_sizes, int n_in,
                              void* d_out, int out_size)
{
    const float* pred = (const float*)d_in[0];
    const float* tru  = (const float*)d_in[1];
    const float* mask = (const float*)d_in[2];
    float* out = (float*)d_out;

    fape_kernel<<<GRID, TPB>>>(pred, tru, mask, out);
}